// round 2
// baseline (speedup 1.0000x reference)
#include <cuda_runtime.h>
#include <math.h>

#define SEQ   2048
#define BATCH 64
#define INP   256
#define HID   256

typedef unsigned long long ull;

// ---------- packed f32x2 helpers (Blackwell FFMA2 path, PTX-only) ----------
__device__ __forceinline__ void ffma2(ull& d, ull a, ull b) {
    asm("fma.rn.f32x2 %0, %1, %2, %0;" : "+l"(d) : "l"(a), "l"(b));
}
__device__ __forceinline__ ull pk(float a, float b) {
    ull r; asm("mov.b64 %0, {%1, %2};" : "=l"(r) : "f"(a), "f"(b)); return r;
}
__device__ __forceinline__ float2 unpk(ull v) {
    float x, y; asm("mov.b64 {%0, %1}, %2;" : "=f"(x), "=f"(y) : "l"(v));
    return make_float2(x, y);
}

// =====================================================================
// Phase 1: xp[t,b,h] = sum_i x[t,b,i] * W_ih[h,i] + b_ih[h] + b_hh[h]
// One CTA per t. 256 threads. Output tile 64(b) x 256(h).
// Thread (warp tm, lane tn) computes rows m0..m0+7 (m0=8*tm) for
// h in {tn + 32*v : v=0..7}.  K tiled by 32.
// =====================================================================
__global__ __launch_bounds__(256) void xp_gemm_kernel(
    const float* __restrict__ x,    // [SEQ][BATCH][INP]
    const float* __restrict__ Wih,  // [HID][INP]
    const float* __restrict__ bih,  // [HID]
    const float* __restrict__ bhh,  // [HID]
    float* __restrict__ out)        // [SEQ][BATCH][HID]
{
    __shared__ float Xs[32][68];    // [k][m], padded: stores conflict-light, reads broadcast
    __shared__ float Ws[32][257];   // [k][h], padded: reads conflict-free (lane-consecutive h)

    const int t   = blockIdx.x;
    const int tid = threadIdx.x;
    const int tn  = tid & 31;   // lane -> h base
    const int tm  = tid >> 5;   // warp -> m tile
    const int m0  = tm * 8;

    const float* xt = x + (size_t)t * BATCH * INP;

    ull acc[8][4];
    #pragma unroll
    for (int u = 0; u < 8; ++u)
        #pragma unroll
        for (int v = 0; v < 4; ++v) acc[u][v] = 0ull;   // (+0.f,+0.f)

    for (int kc = 0; kc < INP; kc += 32) {
        // ---- load X tile (transposed to [k][m]) ----
        #pragma unroll
        for (int r = 0; r < 2; ++r) {
            int idx = tid + 256 * r;          // 0..511
            int m   = idx >> 3;               // 0..63
            int k4  = (idx & 7) * 4;          // 0..28
            float4 v = *(const float4*)(xt + (size_t)m * INP + kc + k4);
            Xs[k4 + 0][m] = v.x; Xs[k4 + 1][m] = v.y;
            Xs[k4 + 2][m] = v.z; Xs[k4 + 3][m] = v.w;
        }
        // ---- load W tile (transposed to [k][h]) ----
        #pragma unroll
        for (int r = 0; r < 8; ++r) {
            int idx = tid + 256 * r;          // 0..2047
            int h   = idx >> 3;               // 0..255
            int k4  = (idx & 7) * 4;
            float4 v = *(const float4*)(Wih + (size_t)h * INP + kc + k4);
            Ws[k4 + 0][h] = v.x; Ws[k4 + 1][h] = v.y;
            Ws[k4 + 2][h] = v.z; Ws[k4 + 3][h] = v.w;
        }
        __syncthreads();

        #pragma unroll
        for (int k = 0; k < 32; ++k) {
            float4 a0 = *(const float4*)&Xs[k][m0];       // warp-broadcast
            float4 a1 = *(const float4*)&Xs[k][m0 + 4];
            ull ap[8];
            ap[0] = pk(a0.x, a0.x); ap[1] = pk(a0.y, a0.y);
            ap[2] = pk(a0.z, a0.z); ap[3] = pk(a0.w, a0.w);
            ap[4] = pk(a1.x, a1.x); ap[5] = pk(a1.y, a1.y);
            ap[6] = pk(a1.z, a1.z); ap[7] = pk(a1.w, a1.w);

            float w[8];
            #pragma unroll
            for (int v = 0; v < 8; ++v) w[v] = Ws[k][tn + 32 * v];  // conflict-free

            #pragma unroll
            for (int v2 = 0; v2 < 4; ++v2) {
                ull wp = pk(w[2 * v2], w[2 * v2 + 1]);  // outputs h=tn+64v2, tn+64v2+32
                #pragma unroll
                for (int u = 0; u < 8; ++u)
                    ffma2(acc[u][v2], wp, ap[u]);
            }
        }
        __syncthreads();
    }

    // epilogue: add bias, store
    float ba[4], bb[4];
    #pragma unroll
    for (int v2 = 0; v2 < 4; ++v2) {
        int hA = tn + 64 * v2, hB = hA + 32;
        ba[v2] = bih[hA] + bhh[hA];
        bb[v2] = bih[hB] + bhh[hB];
    }
    float* ot = out + (size_t)t * BATCH * HID;
    #pragma unroll
    for (int u = 0; u < 8; ++u) {
        float* row = ot + (size_t)(m0 + u) * HID;
        #pragma unroll
        for (int v2 = 0; v2 < 4; ++v2) {
            float2 s = unpk(acc[u][v2]);
            row[tn + 64 * v2]      = s.x + ba[v2];
            row[tn + 64 * v2 + 32] = s.y + bb[v2];
        }
    }
}

// =====================================================================
// Phase 2: serial scan. 64 CTAs (one per batch), 256 threads (one per
// output row j). W_hh row j: k in [0,56) lives in smem (layout
// [pair4][row] -> conflict-free LDS.128), k in [56,256) lives in
// registers as 100 packed f32x2 pairs. h double-buffered in smem,
// one __syncthreads per step.  xp is read from d_out and overwritten
// in place with h_t.
// =====================================================================
#define SMEM_K   56
#define SMEM_F4  (SMEM_K / 4)            // 14 float4 groups per row
#define REG_K    (HID - SMEM_K)          // 200
#define REG_PAIRS (REG_K / 2)            // 100
#define REG_F4   (REG_K / 4)             // 50

__global__ __launch_bounds__(256, 1) void rnn_scan_kernel(
    const float* __restrict__ Whh,  // [HID][HID]
    float* __restrict__ out)        // in: xp, out: h   [SEQ][BATCH][HID]
{
    extern __shared__ float smem[];
    // [ Wsm: SMEM_F4*256 float4 = 57344 B ][ hbuf: 2*256 floats = 2048 B ]
    ulonglong2* W2   = (ulonglong2*)smem;            // W2[g*256 + j] = pairs (4g..4g+3) of row j
    float*      hbuf = smem + SMEM_F4 * 256 * 4;

    const int b = blockIdx.x;
    const int j = threadIdx.x;

    // ---- load smem-resident W slice (k in [0,56)) ----
    for (int i = j; i < 256 * SMEM_F4; i += 256) {
        int r = i / SMEM_F4;
        int g = i % SMEM_F4;
        float4 v = *(const float4*)(Whh + (size_t)r * HID + 4 * g);
        ((float4*)smem)[g * 256 + r] = v;
    }
    // ---- load register-resident W slice (k in [56,256)) ----
    ull wreg[REG_PAIRS];
    {
        const float* wrow = Whh + (size_t)j * HID + SMEM_K;
        #pragma unroll
        for (int p = 0; p < REG_PAIRS; ++p)
            wreg[p] = *(const ull*)(wrow + 2 * p);   // 8B-aligned (SMEM_K even)
    }
    // ---- h0 = 0 ----
    hbuf[j] = 0.f;
    hbuf[256 + j] = 0.f;
    __syncthreads();

    const size_t stride = (size_t)BATCH * HID;
    float* col = out + (size_t)b * HID + j;   // col[t*stride] = xp/h at (t,b,j)

    float xpv = col[0];
    int cur = 0;

    for (int t = 0; t < SEQ; ++t) {
        // prefetch next timestep's xp (slot not yet overwritten)
        float xp_next = 0.f;
        if (t + 1 < SEQ) xp_next = __ldcg(col + (size_t)(t + 1) * stride);

        const ulonglong2* h2 = (const ulonglong2*)(hbuf + cur * 256);
        ull acc0 = 0ull, acc1 = 0ull;

        #pragma unroll
        for (int g = 0; g < SMEM_F4; ++g) {       // smem W part
            ulonglong2 w = W2[g * 256 + j];
            ulonglong2 h = h2[g];
            ffma2(acc0, w.x, h.x);
            ffma2(acc1, w.y, h.y);
        }
        #pragma unroll
        for (int g = 0; g < REG_F4; ++g) {        // register W part
            ulonglong2 h = h2[SMEM_F4 + g];
            ffma2(acc0, wreg[2 * g],     h.x);
            ffma2(acc1, wreg[2 * g + 1], h.y);
        }

        float2 s0 = unpk(acc0), s1 = unpk(acc1);
        float val = tanhf(xpv + ((s0.x + s0.y) + (s1.x + s1.y)));

        col[(size_t)t * stride] = val;            // h_t to gmem (overwrites consumed xp_t)
        hbuf[(cur ^ 1) * 256 + j] = val;          // h_t to next smem buffer
        __syncthreads();
        cur ^= 1;
        xpv = xp_next;
    }
}

// =====================================================================
extern "C" void kernel_launch(void* const* d_in, const int* in_sizes, int n_in,
                              void* d_out, int out_size) {
    const float* x   = (const float*)d_in[0];  // [SEQ][BATCH][INP]
    const float* Wih = (const float*)d_in[1];  // [HID][INP]
    const float* Whh = (const float*)d_in[2];  // [HID][HID]
    const float* bih = (const float*)d_in[3];  // [HID]
    const float* bhh = (const float*)d_in[4];  // [HID]
    float* out = (float*)d_out;                // [SEQ][BATCH][HID]

    static int smem_set = 0;
    const int scan_smem = SMEM_F4 * 256 * 16 + 2 * 256 * 4;  // 59392 B
    if (!smem_set) {
        cudaFuncSetAttribute(rnn_scan_kernel,
                             cudaFuncAttributeMaxDynamicSharedMemorySize,
                             scan_smem);
        smem_set = 1;
    }

    xp_gemm_kernel<<<SEQ, 256>>>(x, Wih, bih, bhh, out);
    rnn_scan_kernel<<<BATCH, 256, scan_smem>>>(Whh, out);
}